// round 8
// baseline (speedup 1.0000x reference)
#include <cuda_runtime.h>
#include <cuda_bf16.h>
#include <cstdint>

// Problem constants (fixed by the dataset)
#define NB   16   // batch
#define NT   32   // time steps
#define NN   512  // neurons
#define NINP 32   // input neurons  (indices 0..31)
#define NOUT 16   // output neurons (indices 32..47)
#define NGRP (NN/32)   // 16 warp-groups of rows

#define CSZ   8          // CTAs per cluster
#define NPB   2          // batches per cluster (both handled by every thread)
#define NLOC  64         // neurons per CTA
#define NH    4          // k-split quarters
#define TPC   (NLOC*NH)  // 256 threads per CTA
#define PC_CAP 48        // max chem pairs kept per row (96 nnz)
#define PG_CAP 32        // max gj pairs kept per row (64 nnz)
#define OBUF  (NN*NPB)                 // floats per O buffer (1024) = 4096 B
#define OBS_FLOATS (NPB * NT * NINP)   // 2048 floats = 8KB
// dyn smem: [mbar 2x8B pad 16][chem][gj][O x2][obs]
#define SMEM_BYTES (16 + (PC_CAP + PG_CAP) * NLOC * 16 + 2 * OBUF * 4 + OBS_FLOATS * 4)

// Interleaved padded sparse format: g_*4[pair * NN + row] = {w0, colB0, w1, colB1}
// colB = col * NPB*4 (byte offset into O[n][NPB]). Padded/unwritten: zeros
// (device globals are zero-initialized and pairs >= k2 are never written).
__device__ float4 g_chem4[(NN/2) * NN];  // 2 MB
__device__ float4 g_gj4  [(NN/2) * NN];  // 2 MB
__device__ float2 g_tmpc [NN * NN];      // row-major scratch
__device__ float2 g_tmpg [NN * NN];
__device__ int    g_kc2[NGRP];           // pairs per 32-row group (chem, capped)
__device__ int    g_kg2[NGRP];           // pairs per 32-row group (gj, capped)

// ---------------------------------------------------------------------------
// PTX helpers
// ---------------------------------------------------------------------------
__device__ __forceinline__ uint32_t smem_u32(const void* p) {
    return (uint32_t)__cvta_generic_to_shared(p);
}
__device__ __forceinline__ uint32_t mapa_rank(uint32_t addr, uint32_t rank) {
    uint32_t r;
    asm("mapa.shared::cluster.u32 %0, %1, %2;" : "=r"(r) : "r"(addr), "r"(rank));
    return r;
}
__device__ __forceinline__ void cluster_barrier() {
    asm volatile("barrier.cluster.arrive.aligned;" ::: "memory");
    asm volatile("barrier.cluster.wait.aligned;" ::: "memory");
}
__device__ __forceinline__ uint32_t ctarank() {
    uint32_t r;
    asm("mov.u32 %0, %%cluster_ctarank;" : "=r"(r));
    return r;
}
__device__ __forceinline__ float tanh_fast(float x) {
    float y;
    asm("tanh.approx.f32 %0, %1;" : "=f"(y) : "f"(x));
    return y;
}
__device__ __forceinline__ void mbar_init(uint32_t addr, uint32_t cnt) {
    asm volatile("mbarrier.init.shared.b64 [%0], %1;" :: "r"(addr), "r"(cnt) : "memory");
}
__device__ __forceinline__ void mbar_expect_tx(uint32_t addr, uint32_t tx) {
    asm volatile("mbarrier.arrive.expect_tx.shared.b64 _, [%0], %1;"
                 :: "r"(addr), "r"(tx) : "memory");
}
// push 8 bytes (two packed floats) to a peer CTA's SMEM with tx accounting
__device__ __forceinline__ void st_async_f32x2(uint32_t daddr, float lo, float hi,
                                               uint32_t maddr) {
    uint64_t v;
    asm("mov.b64 %0, {%1, %2};" : "=l"(v) : "r"(__float_as_uint(lo)), "r"(__float_as_uint(hi)));
    asm volatile("st.async.shared::cluster.mbarrier::complete_tx::bytes.b64 [%0], %1, [%2];"
                 :: "r"(daddr), "l"(v), "r"(maddr) : "memory");
}
__device__ __forceinline__ void mbar_wait_parity(uint32_t addr, uint32_t parity) {
    uint32_t done;
    asm volatile(
        "{\n\t"
        ".reg .pred p;\n\t"
        "mbarrier.try_wait.parity.acquire.cta.shared::cta.b64 p, [%1], %2;\n\t"
        "selp.b32 %0, 1, 0, p;\n\t"
        "}"
        : "=r"(done) : "r"(addr), "r"(parity) : "memory");
    if (!done) {
        asm volatile(
            "{\n\t"
            ".reg .pred P1;\n\t"
            "WL_%=:\n\t"
            "mbarrier.try_wait.parity.acquire.cta.shared::cta.b64 P1, [%0], %1, 0x989680;\n\t"
            "@P1 bra.uni WD_%=;\n\t"
            "bra.uni WL_%=;\n\t"
            "WD_%=:\n\t"
            "}"
            :: "r"(addr), "r"(parity) : "memory");
    }
}

// ---------------------------------------------------------------------------
// Prep: softplus + mask + per-row compaction, then transpose into the
// interleaved warp-padded float4 layout. One block per group of 32 rows.
// ---------------------------------------------------------------------------
__global__ void __launch_bounds__(1024, 1)
prep_kernel(const float* __restrict__ W,
            const float* __restrict__ mex,
            const float* __restrict__ min_,
            const float* __restrict__ mgj)
{
    const int group = blockIdx.x;           // 0..15
    const int wid   = threadIdx.x >> 5;     // row within group
    const int lane  = threadIdx.x & 31;
    const int row   = group * 32 + wid;
    const int base  = row * NN;

    __shared__ int s_cnt_c[32], s_cnt_g[32];
    __shared__ int s_kc2, s_kg2;

    int cbase = 0, gbase = 0;
    for (int s0 = 0; s0 < NN; s0 += 32) {
        int s = s0 + lane;
        float w  = W[base + s];
        float wp = log1pf(expf(w));                 // softplus, w in [0,5]
        float m  = mex[base + s] - min_[base + s];  // {-1,0,1}
        float g  = mgj[base + s];                   // {0,1}
        bool cnz = (m != 0.0f);
        bool gnz = (g != 0.0f);
        unsigned cb = __ballot_sync(0xffffffffu, cnz);
        unsigned gb = __ballot_sync(0xffffffffu, gnz);
        unsigned pre = (1u << lane) - 1u;
        if (cnz) g_tmpc[base + cbase + __popc(cb & pre)] =
                     make_float2(wp * m, __int_as_float(s * (NPB * 4)));
        if (gnz) g_tmpg[base + gbase + __popc(gb & pre)] =
                     make_float2(wp, __int_as_float(s * (NPB * 4)));
        cbase += __popc(cb);
        gbase += __popc(gb);
    }
    if (lane == 0) { s_cnt_c[wid] = cbase; s_cnt_g[wid] = gbase; }
    __syncthreads();

    if (threadIdx.x == 0) {
        int mc = 0, mg = 0;
        for (int i = 0; i < 32; ++i) {
            mc = max(mc, s_cnt_c[i]);
            mg = max(mg, s_cnt_g[i]);
        }
        s_kc2 = min((mc + 1) >> 1, PC_CAP);
        s_kg2 = min((mg + 1) >> 1, PG_CAP);
        g_kc2[group] = s_kc2;
        g_kg2[group] = s_kg2;
    }
    __syncthreads();
    const int kc2 = s_kc2;
    const int kg2 = s_kg2;

    const float2 zero = make_float2(0.0f, __int_as_float(0));
    for (int idx = threadIdx.x; idx < kc2 * 32; idx += 1024) {
        int p  = idx >> 5;
        int r  = idx & 31;
        int rw = group * 32 + r;
        int cnt = s_cnt_c[r];
        float2 e0 = (2 * p     < cnt) ? g_tmpc[rw * NN + 2 * p]     : zero;
        float2 e1 = (2 * p + 1 < cnt) ? g_tmpc[rw * NN + 2 * p + 1] : zero;
        g_chem4[p * NN + rw] = make_float4(e0.x, e0.y, e1.x, e1.y);
    }
    for (int idx = threadIdx.x; idx < kg2 * 32; idx += 1024) {
        int p  = idx >> 5;
        int r  = idx & 31;
        int rw = group * 32 + r;
        int cnt = s_cnt_g[r];
        float2 e0 = (2 * p     < cnt) ? g_tmpg[rw * NN + 2 * p]     : zero;
        float2 e1 = (2 * p + 1 < cnt) ? g_tmpg[rw * NN + 2 * p + 1] : zero;
        g_gj4[p * NN + rw] = make_float4(e0.x, e0.y, e1.x, e1.y);
    }
}

// ---------------------------------------------------------------------------
// Main recurrence. 8 clusters of 8 CTAs; thread = (neuron, k-quarter),
// handling BOTH batches. Weights + obs SMEM-resident. O exchanged via
// st.async.b64 + mbarrier tx accounting — no barrier/sync in the loop.
// ---------------------------------------------------------------------------
__global__ void __launch_bounds__(TPC, 1) __cluster_dims__(CSZ, 1, 1)
step_kernel(const float* __restrict__ obs,   // (B, T, NINP)
            const float* __restrict__ thr,   // (N,)
            const float* __restrict__ dec,   // (N,)
            float* __restrict__ out)         // (B, T, NOUT)
{
    extern __shared__ float4 s4[];
    // layout: [0:16) mbarriers, then chem, gj, O double buffer, obs
    uint64_t* mbar = (uint64_t*)s4;
    float4* s_chem = s4 + 1;                                // [PC_CAP*NLOC]
    float4* s_gj   = s_chem + PC_CAP * NLOC;                // [PG_CAP*NLOC]
    float*  O_all  = (float*)(s_gj + PG_CAP * NLOC);        // [2][OBUF] as [n][2]
    float*  s_obs  = O_all + 2 * OBUF;                      // [OBS_FLOATS]

    const int rank = (int)ctarank();
    const int bb   = (blockIdx.x / CSZ) * NPB;   // batch base of cluster
    const int tid  = threadIdx.x;
    const int h    = tid & 3;                    // k-quarter
    const int nloc = tid >> 2;
    const int d0   = rank * NLOC;
    const int d    = d0 + nloc;

    const int cAp = min(g_kc2[2 * rank],     PC_CAP);
    const int cBp = min(g_kc2[2 * rank + 1], PC_CAP);
    const int gAp = min(g_kg2[2 * rank],     PG_CAP);
    const int gBp = min(g_kg2[2 * rank + 1], PG_CAP);
    const int kcA = (cAp + 3) >> 2, kcB = (cBp + 3) >> 2;   // pairs per quarter
    const int kgA = (gAp + 3) >> 2, kgB = (gBp + 3) >> 2;

    // ---- load sparse slice (+ zero-padded tails) + obs into SMEM (once) ----
    {
        int cload = 4 * max(kcA, kcB);   // <= PC_CAP
        for (int i = tid; i < cload * NLOC; i += TPC)
            s_chem[i] = g_chem4[(i >> 6) * NN + d0 + (i & 63)];
        int gload = 4 * max(kgA, kgB);   // <= PG_CAP
        for (int i = tid; i < gload * NLOC; i += TPC)
            s_gj[i] = g_gj4[(i >> 6) * NN + d0 + (i & 63)];
        if (rank == 0) {
            const float* osrc = obs + bb * NT * NINP;
            for (int i = tid; i < OBS_FLOATS; i += TPC) s_obs[i] = osrc[i];
        }
        if (tid == 0) { mbar_init(smem_u32(&mbar[0]), 1); mbar_init(smem_u32(&mbar[1]), 1); }
    }
    __syncthreads();
    cluster_barrier();   // mbarriers + smem ready in all CTAs before any st.async

    const int kc = (nloc < 32) ? kcA : kcB;   // warp-uniform
    const int kg = (nloc < 32) ? kgA : kgB;
    const int cOff = h * kc;                  // this quarter's pair range
    const int gOff = h * kg;

    // remote addresses: I push my neuron's {O_b0,O_b1} (8B) to ranks 2h, 2h+1
    const uint32_t myO   = smem_u32(&O_all[nloc * NPB]) + (uint32_t)(rank * NLOC * NPB * 4);
    const uint32_t mymbar = smem_u32(&mbar[0]);
    const uint32_t r0 = (uint32_t)(2 * h), r1 = (uint32_t)(2 * h + 1);
    const uint32_t pd0 = mapa_rank(myO, r0),    pd1 = mapa_rank(myO, r1);
    const uint32_t pm0 = mapa_rank(mymbar, r0), pm1 = mapa_rank(mymbar, r1);

    const float th = thr[d];
    const float dc = dec[d];
    const bool is_in  = (d < NINP);                       // rank 0, warps 0-3
    const bool is_out = (d >= NINP) && (d < NINP + NOUT); // rank 0, warps 4-5

    float E0 = 0.0f, O0 = 0.0f, E1 = 0.0f, O1 = 0.0f;

    for (int t = 0; t < NT; ++t) {
        float Eh0, Oh0, Eh1, Oh1;
        if (is_in) {
            float ob0 = s_obs[t * NINP + d];
            float ob1 = s_obs[(NT + t) * NINP + d];
            Eh0 = Oh0 = ob0;
            Eh1 = Oh1 = ob1;
        } else {
            Eh0 = E0; Oh0 = O0;
            Eh1 = E1; Oh1 = O1;
        }

        const uint32_t bo = (t & 1) ? (uint32_t)(OBUF * 4) : 0u;
        const uint32_t mo = (t & 1) ? 8u : 0u;

        if (tid == 0) mbar_expect_tx(mymbar + mo, OBUF * 4);

        // push my neuron's O pair to my 2 ranks (4 quarters cover all 8)
        st_async_f32x2(pd0 + bo, Oh0, Oh1, pm0 + mo);
        st_async_f32x2(pd1 + bo, Oh0, Oh1, pm1 + mo);

        // wait: all OBUF*4 bytes (512 x 8B messages) have landed
        mbar_wait_parity(mymbar + mo, (uint32_t)((t >> 1) & 1));

        if (!is_in) {
            const char* Ob = (const char*)(O_all + (t & 1) * OBUF);

            // chemical current (this quarter's pairs), both batches
            float Ic00 = 0.0f, Ic01 = 0.0f, Ic10 = 0.0f, Ic11 = 0.0f;
            #pragma unroll 4
            for (int p = 0; p < kc; ++p) {
                float4 e = s_chem[(cOff + p) * NLOC + nloc];
                float2 o0 = *(const float2*)(Ob + __float_as_int(e.y));
                float2 o1 = *(const float2*)(Ob + __float_as_int(e.w));
                Ic00 += e.x * o0.x; Ic01 += e.x * o0.y;
                Ic10 += e.z * o1.x; Ic11 += e.z * o1.y;
            }

            // gap junction current (this quarter's pairs), both batches
            const float m10E0 = -10.0f * Eh0;
            const float m10E1 = -10.0f * Eh1;
            float Ig0 = 0.0f, Ig1 = 0.0f;
            #pragma unroll 4
            for (int p = 0; p < kg; ++p) {
                float4 e = s_gj[(gOff + p) * NLOC + nloc];
                float2 o0 = *(const float2*)(Ob + __float_as_int(e.y));
                float2 o1 = *(const float2*)(Ob + __float_as_int(e.w));
                Ig0 += e.x * o0.x * tanh_fast(fmaf(10.0f, o0.x, m10E0));
                Ig1 += e.x * o0.y * tanh_fast(fmaf(10.0f, o0.y, m10E1));
                Ig0 += e.z * o1.x * tanh_fast(fmaf(10.0f, o1.x, m10E0));
                Ig1 += e.z * o1.y * tanh_fast(fmaf(10.0f, o1.y, m10E1));
            }

            // combine the 4 quarters (xor over lane bits 0,1); all replicas
            // then run the epilogue redundantly (identical results)
            float S0 = (Ic00 + Ic10) + Ig0;
            float S1 = (Ic01 + Ic11) + Ig1;
            S0 += __shfl_xor_sync(0xffffffffu, S0, 1);
            S0 += __shfl_xor_sync(0xffffffffu, S0, 2);
            S1 += __shfl_xor_sync(0xffffffffu, S1, 1);
            S1 += __shfl_xor_sync(0xffffffffu, S1, 2);

            // epilogue, batch 0
            {
                float curr = Eh0 + S0;
                curr = fminf(10.0f, fmaxf(-10.0f, curr));
                float z  = curr - th;
                float On = (z >= 0.0f) ? z : 0.01f * z;
                float fg = __fdividef(1.0f, 1.0f + __expf(-10.0f * z));
                float dg = __fdividef(1.0f, 1.0f + __expf(-5.0f * (fabsf(Eh0 - curr) - 0.01f)));
                float Enf = dg * curr + (1.0f - dg) * (Eh0 - dc);
                E0 = fg * On + (1.0f - fg) * Enf;
                O0 = On;
            }
            // epilogue, batch 1
            {
                float curr = Eh1 + S1;
                curr = fminf(10.0f, fmaxf(-10.0f, curr));
                float z  = curr - th;
                float On = (z >= 0.0f) ? z : 0.01f * z;
                float fg = __fdividef(1.0f, 1.0f + __expf(-10.0f * z));
                float dg = __fdividef(1.0f, 1.0f + __expf(-5.0f * (fabsf(Eh1 - curr) - 0.01f)));
                float Enf = dg * curr + (1.0f - dg) * (Eh1 - dc);
                E1 = fg * On + (1.0f - fg) * Enf;
                O1 = On;
            }

            if (is_out && h < 2) {
                float Ev = (h == 0) ? E0 : E1;
                out[((bb + h) * NT + t) * NOUT + (d - NINP)] = Ev;
            }
        }
    }

    cluster_barrier();   // don't tear down while peers may still st.async into me
}

// ---------------------------------------------------------------------------
extern "C" void kernel_launch(void* const* d_in, const int* in_sizes, int n_in,
                              void* d_out, int out_size)
{
    (void)in_sizes; (void)n_in; (void)out_size;
    const float* obs  = (const float*)d_in[0];
    const float* W    = (const float*)d_in[1];
    const float* thr  = (const float*)d_in[2];
    const float* dec  = (const float*)d_in[3];
    const float* mex  = (const float*)d_in[4];
    const float* min_ = (const float*)d_in[5];
    const float* mgj  = (const float*)d_in[6];

    static bool attr_set = false;
    if (!attr_set) {
        cudaFuncSetAttribute(step_kernel,
                             cudaFuncAttributeMaxDynamicSharedMemorySize,
                             SMEM_BYTES);
        attr_set = true;
    }

    prep_kernel<<<NGRP, 1024>>>(W, mex, min_, mgj);
    step_kernel<<<(NB / NPB) * CSZ, TPC, SMEM_BYTES>>>(obs, thr, dec, (float*)d_out);
}